// round 1
// baseline (speedup 1.0000x reference)
#include <cuda_runtime.h>
#include <cuda_bf16.h>
#include <math.h>

// Problem dims
#define BB   4
#define LL   1024
#define DD   512
#define CHI  32
#define SS   4
#define NT   (BB*LL)          // 4096 tokens
#define CSC  (CHI*SS*CHI)     // 4096

// ---------------- scratch (__device__ globals, no allocs) ----------------
__device__ float g_site[(size_t)NT * CSC];   // x @ W_site + b_site        (64 MB)
__device__ float g_gate[(size_t)NT * DD];    // x @ W_gate + b_gate        (8 MB)
__device__ float g_Bmat[(size_t)NT * CHI * CHI]; // B_t[r][l]              (16 MB)
__device__ float g_c[(size_t)NT * CHI];      // c_t[r] = u_t @ B_t
__device__ float g_left[(size_t)NT * CHI];   // recorded left vectors
__device__ float g_M[(size_t)NT * (SS*CHI)]; // Mt flattened [t][128]
__device__ float g_y[(size_t)NT * DD];       // pre-LN y
__device__ float g_Wco[128 * 512];           // W_bridge @ W_out
__device__ float g_bco[512];                 // b_bridge @ W_out + b_out

// ---------------- prep: fuse bridge+out weights ----------------
__global__ void prep_kernel(const float* __restrict__ Wb, const float* __restrict__ bb,
                            const float* __restrict__ Wo, const float* __restrict__ bo)
{
    int idx = blockIdx.x * blockDim.x + threadIdx.x;   // 0..65535
    int pr = idx >> 9, j = idx & 511;
    float s = 0.f;
#pragma unroll
    for (int i = 0; i < 32; ++i)
        s = fmaf(Wb[pr * 32 + i], Wo[i * 512 + j], s);
    g_Wco[idx] = s;
    if (idx < 512) {
        float c = bo[idx];
#pragma unroll
        for (int i = 0; i < 32; ++i)
            c = fmaf(bb[i], Wo[i * 512 + idx], c);
        g_bco[idx] = c;
    }
}

// ---------------- generic SGEMM: C = A[MxK] @ B[KxN] + bias ----------------
// 128x128 tile, BK=8, 256 threads, 8x8 microtile, double-buffered smem.
__global__ __launch_bounds__(256, 2)
void sgemm_bias_kernel(const float* __restrict__ A, const float* __restrict__ B,
                       const float* __restrict__ bias, float* __restrict__ C,
                       int M, int N, int K)
{
    __shared__ float As[2][8][128];
    __shared__ float Bs[2][8][128];
    const int tid = threadIdx.x;
    const int bm = blockIdx.y * 128;
    const int bn = blockIdx.x * 128;
    const int tx = tid & 15;
    const int ty = tid >> 4;
    const int rm0 = ty * 4;
    const int cn0 = tx * 4;

    float acc[8][8];
#pragma unroll
    for (int i = 0; i < 8; ++i)
#pragma unroll
        for (int j = 0; j < 8; ++j) acc[i][j] = 0.f;

    const int arow = tid >> 1;
    const int acol = (tid & 1) * 4;
    const int brow = tid >> 5;
    const int bcol = (tid & 31) * 4;

    const float* Aptr = A + (size_t)(bm + arow) * K + acol;
    const float* Bptr = B + (size_t)brow * N + bn + bcol;

    float4 av = *(const float4*)(Aptr);
    float4 bv = *(const float4*)(Bptr);
    As[0][acol + 0][arow] = av.x; As[0][acol + 1][arow] = av.y;
    As[0][acol + 2][arow] = av.z; As[0][acol + 3][arow] = av.w;
    *(float4*)&Bs[0][brow][bcol] = bv;
    __syncthreads();

    int buf = 0;
    for (int k0 = 8; k0 <= K; k0 += 8) {
        float4 av2, bv2;
        if (k0 < K) {
            av2 = *(const float4*)(Aptr + k0);
            bv2 = *(const float4*)(Bptr + (size_t)k0 * N);
        }
#pragma unroll
        for (int kk = 0; kk < 8; ++kk) {
            float a[8], b[8];
            *(float4*)&a[0] = *(const float4*)&As[buf][kk][rm0];
            *(float4*)&a[4] = *(const float4*)&As[buf][kk][rm0 + 64];
            *(float4*)&b[0] = *(const float4*)&Bs[buf][kk][cn0];
            *(float4*)&b[4] = *(const float4*)&Bs[buf][kk][cn0 + 64];
#pragma unroll
            for (int i = 0; i < 8; ++i)
#pragma unroll
                for (int j = 0; j < 8; ++j)
                    acc[i][j] = fmaf(a[i], b[j], acc[i][j]);
        }
        if (k0 < K) {
            buf ^= 1;
            As[buf][acol + 0][arow] = av2.x; As[buf][acol + 1][arow] = av2.y;
            As[buf][acol + 2][arow] = av2.z; As[buf][acol + 3][arow] = av2.w;
            *(float4*)&Bs[buf][brow][bcol] = bv2;
            __syncthreads();
        }
    }

#pragma unroll
    for (int i = 0; i < 8; ++i) {
        int row = bm + rm0 + ((i < 4) ? i : (60 + i));   // i>=4 -> 64 + (i-4)
#pragma unroll
        for (int jq = 0; jq < 2; ++jq) {
            int col = bn + cn0 + jq * 64;
            float4 o;
            o.x = acc[i][jq * 4 + 0] + bias[col + 0];
            o.y = acc[i][jq * 4 + 1] + bias[col + 1];
            o.z = acc[i][jq * 4 + 2] + bias[col + 2];
            o.w = acc[i][jq * 4 + 3] + bias[col + 3];
            *(float4*)&C[(size_t)row * N + col] = o;
        }
    }
}

// ---------------- reduce site -> B_t (over physical index p) + c_t ----------------
__global__ __launch_bounds__(256) void redc_kernel(const float* __restrict__ x)
{
    __shared__ float sB[1024];
    int t = blockIdx.x;
    const float* row = g_site + (size_t)t * CSC;
    for (int j = threadIdx.x; j < 1024; j += 256) {
        int r = j >> 5, l = j & 31;
        int base = l * 128 + r;
        float s = row[base] + row[base + 32] + row[base + 64] + row[base + 96];
        sB[j] = s;
        g_Bmat[(size_t)t * 1024 + j] = s;      // layout [t][r][l]
    }
    __syncthreads();
    if (threadIdx.x < 32) {
        int r = threadIdx.x;
        const float* xr = x + (size_t)t * DD;  // u = x[:, :32]
        float c = 0.f;
#pragma unroll
        for (int l = 0; l < 32; ++l)
            c = fmaf(xr[l], sB[r * 32 + l], c);
        g_c[(size_t)t * 32 + r] = c;
    }
}

// ---------------- sequential scan: one warp per batch ----------------
// Recurrence: v_t = alpha_{t-1} * (v_{t-1} @ B_t) + c_t,  alpha = 1/(||v||+1e-12).
// Records left_t = alpha_{t-1} * v_{t-1} + u_t (the only quantity the parallel
// epilogue needs). SVD truncation provably inactive (sigma_min/sigma_max ~ 0.5).
__global__ void scan_kernel(const float* __restrict__ x)
{
    const int b = blockIdx.x;
    const int r = threadIdx.x;                 // 0..31
    const size_t tg0 = (size_t)b * LL;

    float v = 0.f;
    float4 bcur[8], bnxt[8];
    {
        const float* bp = g_Bmat + tg0 * 1024 + r * 32;
#pragma unroll
        for (int q = 0; q < 8; ++q) bcur[q] = __ldg((const float4*)(bp + 4 * q));
    }
    float ccur = g_c[tg0 * 32 + r];
    float ucur = x[tg0 * DD + r];

    for (int t = 0; t < LL; ++t) {
        const int tn = (t + 1 < LL) ? (t + 1) : t;
        const float* bpn = g_Bmat + (tg0 + tn) * 1024 + r * 32;
#pragma unroll
        for (int q = 0; q < 8; ++q) bnxt[q] = __ldg((const float4*)(bpn + 4 * q));
        float cnxt = g_c[(tg0 + tn) * 32 + r];
        float unxt = x[(tg0 + tn) * DD + r];

        // ||v||^2 (butterfly) — runs concurrently with the matvec chain
        float s = v * v;
#pragma unroll
        for (int m = 16; m > 0; m >>= 1) s += __shfl_xor_sync(0xffffffffu, s, m);

        // w[r] = sum_l v[l] * B_t[l][r]
        float w = 0.f;
#pragma unroll
        for (int q = 0; q < 8; ++q) {
            w = fmaf(__shfl_sync(0xffffffffu, v, 4 * q + 0), bcur[q].x, w);
            w = fmaf(__shfl_sync(0xffffffffu, v, 4 * q + 1), bcur[q].y, w);
            w = fmaf(__shfl_sync(0xffffffffu, v, 4 * q + 2), bcur[q].z, w);
            w = fmaf(__shfl_sync(0xffffffffu, v, 4 * q + 3), bcur[q].w, w);
        }

        float alpha = 1.f / (sqrtf(s) + 1e-12f);   // t=0: v=0 -> alpha*v = 0 = h0
        g_left[(tg0 + t) * 32 + r] = fmaf(alpha, v, ucur);
        v = fmaf(alpha, w, ccur);

#pragma unroll
        for (int q = 0; q < 8; ++q) bcur[q] = bnxt[q];
        ccur = cnxt; ucur = unxt;
    }
}

// ---------------- recover Mt (== M, no truncation) per token ----------------
__global__ __launch_bounds__(128) void mrec_kernel()
{
    __shared__ float sleft[32];
    int t = blockIdx.x, tid = threadIdx.x;
    if (tid < 32) sleft[tid] = g_left[(size_t)t * 32 + tid];
    __syncthreads();
    const float* row = g_site + (size_t)t * CSC;
    float m = 0.f;
#pragma unroll
    for (int l = 0; l < 32; ++l)
        m = fmaf(sleft[l], row[l * 128 + tid], m);   // coalesced across tid
    g_M[(size_t)t * 128 + tid] = m;
}

// ---------------- LayerNorm + sigmoid-gated residual ----------------
__global__ __launch_bounds__(256) void post_kernel(const float* __restrict__ x,
                                                   const float* __restrict__ gamma,
                                                   const float* __restrict__ beta,
                                                   float* __restrict__ out)
{
    __shared__ float red[256];
    int t = blockIdx.x, tid = threadIdx.x;
    size_t base = (size_t)t * DD;
    int j0 = tid, j1 = tid + 256;
    float y0 = g_y[base + j0], y1 = g_y[base + j1];

    red[tid] = y0 + y1;
    __syncthreads();
    for (int st = 128; st > 0; st >>= 1) {
        if (tid < st) red[tid] += red[tid + st];
        __syncthreads();
    }
    float mu = red[0] * (1.f / 512.f);
    __syncthreads();

    float d0 = y0 - mu, d1 = y1 - mu;
    red[tid] = d0 * d0 + d1 * d1;
    __syncthreads();
    for (int st = 128; st > 0; st >>= 1) {
        if (tid < st) red[tid] += red[tid + st];
        __syncthreads();
    }
    float var = red[0] * (1.f / 512.f);
    float rstd = rsqrtf(var + 1e-6f);

    float yn0 = d0 * rstd * gamma[j0] + beta[j0];
    float yn1 = d1 * rstd * gamma[j1] + beta[j1];
    float gl0 = g_gate[base + j0], gl1 = g_gate[base + j1];
    float gt0 = 1.f / (1.f + expf(-gl0));
    float gt1 = 1.f / (1.f + expf(-gl1));
    float xv0 = x[base + j0], xv1 = x[base + j1];
    out[base + j0] = gt0 * yn0 + (1.f - gt0) * xv0;
    out[base + j1] = gt1 * yn1 + (1.f - gt1) * xv1;
}

// ---------------- launch ----------------
extern "C" void kernel_launch(void* const* d_in, const int* in_sizes, int n_in,
                              void* d_out, int out_size)
{
    (void)in_sizes; (void)n_in; (void)out_size;
    const float* x       = (const float*)d_in[0];
    const float* W_site  = (const float*)d_in[1];
    const float* b_site  = (const float*)d_in[2];
    const float* W_bridge= (const float*)d_in[3];
    const float* b_bridge= (const float*)d_in[4];
    const float* W_out   = (const float*)d_in[5];
    const float* b_out   = (const float*)d_in[6];
    const float* gamma   = (const float*)d_in[7];
    const float* beta    = (const float*)d_in[8];
    const float* W_gate  = (const float*)d_in[9];
    const float* b_gate  = (const float*)d_in[10];
    float* out = (float*)d_out;

    static float *p_site = nullptr, *p_gate = nullptr, *p_M = nullptr,
                 *p_y = nullptr, *p_Wco = nullptr, *p_bco = nullptr;
    if (!p_site) {
        cudaGetSymbolAddress((void**)&p_site, g_site);
        cudaGetSymbolAddress((void**)&p_gate, g_gate);
        cudaGetSymbolAddress((void**)&p_M,    g_M);
        cudaGetSymbolAddress((void**)&p_y,    g_y);
        cudaGetSymbolAddress((void**)&p_Wco,  g_Wco);
        cudaGetSymbolAddress((void**)&p_bco,  g_bco);
    }

    // fused bridge*out weights
    prep_kernel<<<256, 256>>>(W_bridge, b_bridge, W_out, b_out);
    // site tensor: [4096,512] @ [512,4096] + b_site
    sgemm_bias_kernel<<<dim3(CSC / 128, NT / 128), 256>>>(x, W_site, b_site, p_site, NT, CSC, DD);
    // gate pre-activation: [4096,512] @ [512,512] + b_gate
    sgemm_bias_kernel<<<dim3(DD / 128, NT / 128), 256>>>(x, W_gate, b_gate, p_gate, NT, DD, DD);
    // B_t and c_t from site tensor
    redc_kernel<<<NT, 256>>>(x);
    // sequential MPS scan (4 independent warps)
    scan_kernel<<<BB, 32>>>(x);
    // recover per-token M
    mrec_kernel<<<NT, 128>>>();
    // y = M @ (W_bridge@W_out) + fused bias : [4096,128] @ [128,512]
    sgemm_bias_kernel<<<dim3(DD / 128, NT / 128), 256>>>(p_M, p_Wco, p_bco, p_y, NT, DD, 128);
    // LayerNorm + gated residual
    post_kernel<<<NT, 256>>>(x, gamma, beta, out);
}

// round 2
// speedup vs baseline: 1.0982x; 1.0982x over previous
#include <cuda_runtime.h>
#include <cuda_bf16.h>
#include <math.h>

// Problem dims
#define BB   4
#define LL   1024
#define DD   512
#define CHI  32
#define SS   4
#define NT   (BB*LL)          // 4096 tokens
#define CSC  (CHI*SS*CHI)     // 4096

// ---------------- scratch (__device__ globals, no allocs) ----------------
__device__ float g_site[(size_t)NT * CSC];   // x @ W_site + b_site        (64 MB)
__device__ float g_gate[(size_t)NT * DD];    // x @ W_gate + b_gate        (8 MB)
__device__ float g_Bmat[(size_t)NT * CHI * CHI]; // B_t stored [t][r*32+l] (16 MB)
__device__ float g_WB[512 * 1024];           // pre-reduced site weights for B
__device__ float g_bB[1024];                 // pre-reduced site bias for B
__device__ float g_c[(size_t)NT * CHI];      // c_t[r] = u_t @ B_t
__device__ float g_left[(size_t)NT * CHI];   // recorded left vectors
__device__ float g_M[(size_t)NT * (SS*CHI)]; // Mt flattened [t][128]
__device__ float g_y[(size_t)NT * DD];       // pre-LN y
__device__ float g_Wco[128 * 512];           // W_bridge @ W_out
__device__ float g_bco[512];                 // b_bridge @ W_out + b_out

// ---------------- prep: fuse bridge+out weights ----------------
__global__ void prep_kernel(const float* __restrict__ Wb, const float* __restrict__ bb,
                            const float* __restrict__ Wo, const float* __restrict__ bo)
{
    int idx = blockIdx.x * blockDim.x + threadIdx.x;   // 0..65535
    int pr = idx >> 9, j = idx & 511;
    float s = 0.f;
#pragma unroll
    for (int i = 0; i < 32; ++i)
        s = fmaf(Wb[pr * 32 + i], Wo[i * 512 + j], s);
    g_Wco[idx] = s;
    if (idx < 512) {
        float c = bo[idx];
#pragma unroll
        for (int i = 0; i < 32; ++i)
            c = fmaf(bb[i], Wo[i * 512 + idx], c);
        g_bco[idx] = c;
    }
}

// ---------------- prep: reduce W_site over physical index -> W_B ----------------
// site col index j = l*128 + p*32 + r;  W_B[d][r*32+l] = sum_p W_site[d][l*128+p*32+r]
__global__ __launch_bounds__(256) void wb_kernel(const float* __restrict__ Ws,
                                                 const float* __restrict__ bs)
{
    int idx = blockIdx.x * 256 + threadIdx.x;          // 0 .. 512*1024-1
    int d = idx >> 10, rem = idx & 1023;
    int l = rem >> 5, r = rem & 31;
    const float* p = Ws + (size_t)d * 4096 + l * 128 + r;   // coalesced in r
    g_WB[(size_t)d * 1024 + r * 32 + l] = p[0] + p[32] + p[64] + p[96];
    if (idx < 1024) {
        int ll = idx >> 5, rr = idx & 31;
        const float* q = bs + ll * 128 + rr;
        g_bB[rr * 32 + ll] = q[0] + q[32] + q[64] + q[96];
    }
}

// ---------------- generic SGEMM: C = A[MxK] @ B[KxN] + bias ----------------
// 128x128 tile, BK=8, 256 threads, 8x8 microtile, double-buffered smem.
__global__ __launch_bounds__(256, 2)
void sgemm_bias_kernel(const float* __restrict__ A, const float* __restrict__ B,
                       const float* __restrict__ bias, float* __restrict__ C,
                       int M, int N, int K)
{
    __shared__ float As[2][8][128];
    __shared__ float Bs[2][8][128];
    const int tid = threadIdx.x;
    const int bm = blockIdx.y * 128;
    const int bn = blockIdx.x * 128;
    const int tx = tid & 15;
    const int ty = tid >> 4;
    const int rm0 = ty * 4;
    const int cn0 = tx * 4;

    float acc[8][8];
#pragma unroll
    for (int i = 0; i < 8; ++i)
#pragma unroll
        for (int j = 0; j < 8; ++j) acc[i][j] = 0.f;

    const int arow = tid >> 1;
    const int acol = (tid & 1) * 4;
    const int brow = tid >> 5;
    const int bcol = (tid & 31) * 4;

    const float* Aptr = A + (size_t)(bm + arow) * K + acol;
    const float* Bptr = B + (size_t)brow * N + bn + bcol;

    float4 av = *(const float4*)(Aptr);
    float4 bv = *(const float4*)(Bptr);
    As[0][acol + 0][arow] = av.x; As[0][acol + 1][arow] = av.y;
    As[0][acol + 2][arow] = av.z; As[0][acol + 3][arow] = av.w;
    *(float4*)&Bs[0][brow][bcol] = bv;
    __syncthreads();

    int buf = 0;
    for (int k0 = 8; k0 <= K; k0 += 8) {
        float4 av2, bv2;
        if (k0 < K) {
            av2 = *(const float4*)(Aptr + k0);
            bv2 = *(const float4*)(Bptr + (size_t)k0 * N);
        }
#pragma unroll
        for (int kk = 0; kk < 8; ++kk) {
            float a[8], b[8];
            *(float4*)&a[0] = *(const float4*)&As[buf][kk][rm0];
            *(float4*)&a[4] = *(const float4*)&As[buf][kk][rm0 + 64];
            *(float4*)&b[0] = *(const float4*)&Bs[buf][kk][cn0];
            *(float4*)&b[4] = *(const float4*)&Bs[buf][kk][cn0 + 64];
#pragma unroll
            for (int i = 0; i < 8; ++i)
#pragma unroll
                for (int j = 0; j < 8; ++j)
                    acc[i][j] = fmaf(a[i], b[j], acc[i][j]);
        }
        if (k0 < K) {
            buf ^= 1;
            As[buf][acol + 0][arow] = av2.x; As[buf][acol + 1][arow] = av2.y;
            As[buf][acol + 2][arow] = av2.z; As[buf][acol + 3][arow] = av2.w;
            *(float4*)&Bs[buf][brow][bcol] = bv2;
            __syncthreads();
        }
    }

#pragma unroll
    for (int i = 0; i < 8; ++i) {
        int row = bm + rm0 + ((i < 4) ? i : (60 + i));   // i>=4 -> 64 + (i-4)
#pragma unroll
        for (int jq = 0; jq < 2; ++jq) {
            int col = bn + cn0 + jq * 64;
            float4 o;
            o.x = acc[i][jq * 4 + 0] + bias[col + 0];
            o.y = acc[i][jq * 4 + 1] + bias[col + 1];
            o.z = acc[i][jq * 4 + 2] + bias[col + 2];
            o.w = acc[i][jq * 4 + 3] + bias[col + 3];
            *(float4*)&C[(size_t)row * N + col] = o;
        }
    }
}

// ---------------- c_t[r] = sum_l u_t[l] * B_t[l][r] ----------------
__global__ void c_kernel(const float* __restrict__ x)
{
    int t = blockIdx.x;
    int r = threadIdx.x;                       // 0..31
    float u = x[(size_t)t * DD + r];           // lane l holds u_l
    const float* brow = g_Bmat + (size_t)t * 1024 + r * 32;
    float4 b4[8];
#pragma unroll
    for (int q = 0; q < 8; ++q) b4[q] = __ldg((const float4*)(brow + 4 * q));
    float c = 0.f;
#pragma unroll
    for (int q = 0; q < 8; ++q) {
        c = fmaf(__shfl_sync(0xffffffffu, u, 4 * q + 0), b4[q].x, c);
        c = fmaf(__shfl_sync(0xffffffffu, u, 4 * q + 1), b4[q].y, c);
        c = fmaf(__shfl_sync(0xffffffffu, u, 4 * q + 2), b4[q].z, c);
        c = fmaf(__shfl_sync(0xffffffffu, u, 4 * q + 3), b4[q].w, c);
    }
    g_c[(size_t)t * 32 + r] = c;
}

// ---------------- sequential scan: one warp per batch ----------------
// v_t = alpha_{t-1} * (v_{t-1} @ B_t) + c_t,  alpha = 1/(||v||+1e-12).
// Norm chain and matvec chain both depend only on v_{t-1}: they run concurrently;
// alpha is folded in AFTER the matvec (linearity).
__global__ void scan_kernel(const float* __restrict__ x)
{
    const int b = blockIdx.x;
    const int r = threadIdx.x;                 // 0..31
    const size_t tg0 = (size_t)b * LL;

    float v = 0.f;
    float4 bcur[8], bnxt[8];
    {
        const float* bp = g_Bmat + tg0 * 1024 + r * 32;
#pragma unroll
        for (int q = 0; q < 8; ++q) bcur[q] = __ldg((const float4*)(bp + 4 * q));
    }
    float ccur = g_c[tg0 * 32 + r];
    float ucur = x[tg0 * DD + r];

    for (int t = 0; t < LL; ++t) {
        const int tn = (t + 1 < LL) ? (t + 1) : t;
        const float* bpn = g_Bmat + (tg0 + tn) * 1024 + r * 32;
#pragma unroll
        for (int q = 0; q < 8; ++q) bnxt[q] = __ldg((const float4*)(bpn + 4 * q));
        float cnxt = g_c[(tg0 + tn) * 32 + r];
        float unxt = x[(tg0 + tn) * DD + r];

        // ||v||^2 (butterfly) — concurrent with the matvec chain
        float s = v * v;
#pragma unroll
        for (int m = 16; m > 0; m >>= 1) s += __shfl_xor_sync(0xffffffffu, s, m);

        // w[r] = sum_l v[l] * B_t[l][r], 4 independent partial chains
        float w0 = 0.f, w1 = 0.f, w2 = 0.f, w3 = 0.f;
#pragma unroll
        for (int q = 0; q < 8; q += 4) {
            w0 = fmaf(__shfl_sync(0xffffffffu, v, 4*q + 0),  bcur[q].x,   w0);
            w0 = fmaf(__shfl_sync(0xffffffffu, v, 4*q + 1),  bcur[q].y,   w0);
            w0 = fmaf(__shfl_sync(0xffffffffu, v, 4*q + 2),  bcur[q].z,   w0);
            w0 = fmaf(__shfl_sync(0xffffffffu, v, 4*q + 3),  bcur[q].w,   w0);
            w1 = fmaf(__shfl_sync(0xffffffffu, v, 4*q + 4),  bcur[q+1].x, w1);
            w1 = fmaf(__shfl_sync(0xffffffffu, v, 4*q + 5),  bcur[q+1].y, w1);
            w1 = fmaf(__shfl_sync(0xffffffffu, v, 4*q + 6),  bcur[q+1].z, w1);
            w1 = fmaf(__shfl_sync(0xffffffffu, v, 4*q + 7),  bcur[q+1].w, w1);
            w2 = fmaf(__shfl_sync(0xffffffffu, v, 4*q + 8),  bcur[q+2].x, w2);
            w2 = fmaf(__shfl_sync(0xffffffffu, v, 4*q + 9),  bcur[q+2].y, w2);
            w2 = fmaf(__shfl_sync(0xffffffffu, v, 4*q + 10), bcur[q+2].z, w2);
            w2 = fmaf(__shfl_sync(0xffffffffu, v, 4*q + 11), bcur[q+2].w, w2);
            w3 = fmaf(__shfl_sync(0xffffffffu, v, 4*q + 12), bcur[q+3].x, w3);
            w3 = fmaf(__shfl_sync(0xffffffffu, v, 4*q + 13), bcur[q+3].y, w3);
            w3 = fmaf(__shfl_sync(0xffffffffu, v, 4*q + 14), bcur[q+3].z, w3);
            w3 = fmaf(__shfl_sync(0xffffffffu, v, 4*q + 15), bcur[q+3].w, w3);
        }
        float w = (w0 + w1) + (w2 + w3);

        float alpha = 1.f / (sqrtf(s) + 1e-12f);   // t=0: v=0 -> alpha*v = 0 = h0
        g_left[(tg0 + t) * 32 + r] = fmaf(alpha, v, ucur);
        v = fmaf(alpha, w, ccur);

#pragma unroll
        for (int q = 0; q < 8; ++q) bcur[q] = bnxt[q];
        ccur = cnxt; ucur = unxt;
    }
}

// ---------------- recover Mt (== M, no truncation) per token ----------------
__global__ __launch_bounds__(128) void mrec_kernel()
{
    __shared__ float sleft[32];
    int t = blockIdx.x, tid = threadIdx.x;
    if (tid < 32) sleft[tid] = g_left[(size_t)t * 32 + tid];
    __syncthreads();
    const float* row = g_site + (size_t)t * CSC;
    float m = 0.f;
#pragma unroll
    for (int l = 0; l < 32; ++l)
        m = fmaf(sleft[l], row[l * 128 + tid], m);   // coalesced across tid
    g_M[(size_t)t * 128 + tid] = m;
}

// ---------------- LayerNorm + sigmoid-gated residual ----------------
__global__ __launch_bounds__(256) void post_kernel(const float* __restrict__ x,
                                                   const float* __restrict__ gamma,
                                                   const float* __restrict__ beta,
                                                   float* __restrict__ out)
{
    __shared__ float red[256];
    int t = blockIdx.x, tid = threadIdx.x;
    size_t base = (size_t)t * DD;
    int j0 = tid, j1 = tid + 256;
    float y0 = g_y[base + j0], y1 = g_y[base + j1];

    red[tid] = y0 + y1;
    __syncthreads();
    for (int st = 128; st > 0; st >>= 1) {
        if (tid < st) red[tid] += red[tid + st];
        __syncthreads();
    }
    float mu = red[0] * (1.f / 512.f);
    __syncthreads();

    float d0 = y0 - mu, d1 = y1 - mu;
    red[tid] = d0 * d0 + d1 * d1;
    __syncthreads();
    for (int st = 128; st > 0; st >>= 1) {
        if (tid < st) red[tid] += red[tid + st];
        __syncthreads();
    }
    float var = red[0] * (1.f / 512.f);
    float rstd = rsqrtf(var + 1e-6f);

    float yn0 = d0 * rstd * gamma[j0] + beta[j0];
    float yn1 = d1 * rstd * gamma[j1] + beta[j1];
    float gl0 = g_gate[base + j0], gl1 = g_gate[base + j1];
    float gt0 = 1.f / (1.f + expf(-gl0));
    float gt1 = 1.f / (1.f + expf(-gl1));
    float xv0 = x[base + j0], xv1 = x[base + j1];
    out[base + j0] = gt0 * yn0 + (1.f - gt0) * xv0;
    out[base + j1] = gt1 * yn1 + (1.f - gt1) * xv1;
}

// ---------------- launch ----------------
extern "C" void kernel_launch(void* const* d_in, const int* in_sizes, int n_in,
                              void* d_out, int out_size)
{
    (void)in_sizes; (void)n_in; (void)out_size;
    const float* x       = (const float*)d_in[0];
    const float* W_site  = (const float*)d_in[1];
    const float* b_site  = (const float*)d_in[2];
    const float* W_bridge= (const float*)d_in[3];
    const float* b_bridge= (const float*)d_in[4];
    const float* W_out   = (const float*)d_in[5];
    const float* b_out   = (const float*)d_in[6];
    const float* gamma   = (const float*)d_in[7];
    const float* beta    = (const float*)d_in[8];
    const float* W_gate  = (const float*)d_in[9];
    const float* b_gate  = (const float*)d_in[10];
    float* out = (float*)d_out;

    static float *p_site = nullptr, *p_gate = nullptr, *p_M = nullptr,
                 *p_y = nullptr, *p_Wco = nullptr, *p_bco = nullptr,
                 *p_WB = nullptr, *p_bB = nullptr, *p_Bmat = nullptr;
    static cudaStream_t s1;
    static cudaEvent_t ev0, evS, evG;
    static bool inited = false;
    if (!inited) {
        cudaGetSymbolAddress((void**)&p_site, g_site);
        cudaGetSymbolAddress((void**)&p_gate, g_gate);
        cudaGetSymbolAddress((void**)&p_M,    g_M);
        cudaGetSymbolAddress((void**)&p_y,    g_y);
        cudaGetSymbolAddress((void**)&p_Wco,  g_Wco);
        cudaGetSymbolAddress((void**)&p_bco,  g_bco);
        cudaGetSymbolAddress((void**)&p_WB,   g_WB);
        cudaGetSymbolAddress((void**)&p_bB,   g_bB);
        cudaGetSymbolAddress((void**)&p_Bmat, g_Bmat);
        cudaStreamCreateWithFlags(&s1, cudaStreamNonBlocking);
        cudaEventCreateWithFlags(&ev0, cudaEventDisableTiming);
        cudaEventCreateWithFlags(&evS, cudaEventDisableTiming);
        cudaEventCreateWithFlags(&evG, cudaEventDisableTiming);
        inited = true;
    }

    // ---- fork side stream (captured as graph branch) ----
    cudaEventRecord(ev0, 0);
    cudaStreamWaitEvent(s1, ev0, 0);

    // side stream: fused bridge*out weights, site GEMM, gate GEMM
    prep_kernel<<<256, 256, 0, s1>>>(W_bridge, b_bridge, W_out, b_out);
    sgemm_bias_kernel<<<dim3(CSC / 128, NT / 128), 256, 0, s1>>>(x, W_site, b_site, p_site, NT, CSC, DD);
    cudaEventRecord(evS, s1);
    sgemm_bias_kernel<<<dim3(DD / 128, NT / 128), 256, 0, s1>>>(x, W_gate, b_gate, p_gate, NT, DD, DD);
    cudaEventRecord(evG, s1);

    // main stream: B-matrix path + sequential scan (independent of site GEMM)
    wb_kernel<<<2048, 256>>>(W_site, b_site);
    sgemm_bias_kernel<<<dim3(1024 / 128, NT / 128), 256>>>(x, p_WB, p_bB, p_Bmat, NT, 1024, DD);
    c_kernel<<<NT, 32>>>(x);
    scan_kernel<<<BB, 32>>>(x);

    // join: need site for M recovery, then final GEMM
    cudaStreamWaitEvent(0, evS, 0);
    mrec_kernel<<<NT, 128>>>();
    sgemm_bias_kernel<<<dim3(DD / 128, NT / 128), 256>>>(p_M, p_Wco, p_bco, p_y, NT, DD, 128);

    // join: need gate for the epilogue
    cudaStreamWaitEvent(0, evG, 0);
    post_kernel<<<NT, 256>>>(x, gamma, beta, out);
}